// round 10
// baseline (speedup 1.0000x reference)
#include <cuda_runtime.h>

// ---------------- f32x2 helpers (Blackwell packed fp32) ----------------------
static __device__ __forceinline__ unsigned long long pk2(float a, float b){
    unsigned long long r; asm("mov.b64 %0,{%1,%2};" : "=l"(r) : "f"(a), "f"(b)); return r;
}
static __device__ __forceinline__ float2 up2(unsigned long long v){
    float2 r; asm("mov.b64 {%0,%1},%2;" : "=f"(r.x), "=f"(r.y) : "l"(v)); return r;
}
static __device__ __forceinline__ void fma2(unsigned long long &d, unsigned long long a, unsigned long long b){
    asm("fma.rn.f32x2 %0,%1,%2,%0;" : "+l"(d) : "l"(a), "l"(b));
}
static __device__ __forceinline__ unsigned long long ld2(const float* p){
    return *reinterpret_cast<const unsigned long long*>(p);
}
// ---------------- cp.async helpers -------------------------------------------
static __device__ __forceinline__ void cpa4(unsigned dst, const float* src, unsigned srcsz){
    asm volatile("cp.async.ca.shared.global [%0],[%1],4,%2;"
                 :: "r"(dst), "l"(src), "r"(srcsz));
}
static __device__ __forceinline__ void cpa_commit(){
    asm volatile("cp.async.commit_group;");
}
template<int N> static __device__ __forceinline__ void cpa_wait(){
    asm volatile("cp.async.wait_group %0;" :: "n"(N));
}

// ---------------- scratch (device globals: no allocations allowed) -----------
__device__ float g_c1[32u*32*128*128];   // conv1 out PLANAR [B][32][128][128]
__device__ float g_c2[32u*64*64*64];     // conv2 out NHWC   [B][64][64][64]
__device__ float g_part[1024u*4096u];    // FC1 split-K partials (1024 chunks)
__device__ float g_part2[32*4096];       // FC1 reduction stage A out
__device__ float g_x[32*128];            // FC1 out (post relu)
__device__ float g_theta[32*6];          // FC2 out

__global__ void k_nop(){}                // shifts profiled slot (index 3) onto k_fc1

// ================= conv1: 3x3 s2 SAME, 3->32, relu ===========================
__global__ void __launch_bounds__(256) k_conv1(const float* __restrict__ in,
                                               const float* __restrict__ k1,
                                               const float* __restrict__ b1){
    __shared__ float sw[864];   // [ky][kx][ci][32]
    __shared__ float sb[32];
    for(int i=threadIdx.x;i<864;i+=256) sw[i]=k1[i];
    if(threadIdx.x<32) sb[threadIdx.x]=b1[threadIdx.x];
    __syncthreads();

    int idx = blockIdx.x*256 + threadIdx.x;          // 32*128*128
    int ox = idx & 127, oy = (idx>>7)&127, b = idx>>14;

    unsigned long long acc[16];
    #pragma unroll
    for(int j=0;j<16;j++) acc[j]=pk2(sb[2*j],sb[2*j+1]);

    const float* ib = in + (size_t)b*256*256*3;
    #pragma unroll
    for(int ky=0;ky<3;ky++){
        int iy = 2*oy+ky;
        if(iy>=256) break;
        #pragma unroll
        for(int kx=0;kx<3;kx++){
            int ix = 2*ox+kx;
            if(ix>=256) continue;
            const float* p = ib + (iy*256+ix)*3;
            #pragma unroll
            for(int ci=0;ci<3;ci++){
                float v = p[ci];
                unsigned long long vv = pk2(v,v);
                const float* w = sw + ((ky*3+kx)*3+ci)*32;
                #pragma unroll
                for(int j=0;j<8;j++){
                    ulonglong2 wv = *reinterpret_cast<const ulonglong2*>(w+4*j);
                    fma2(acc[2*j],   vv, wv.x);
                    fma2(acc[2*j+1], vv, wv.y);
                }
            }
        }
    }
    float* o = g_c1 + (size_t)b*32*16384 + (oy*128+ox);
    #pragma unroll
    for(int j=0;j<16;j++){
        float2 v = up2(acc[j]);
        o[(2*j)*16384]   = v.x>0.f? v.x:0.f;
        o[(2*j+1)*16384] = v.y>0.f? v.y:0.f;
    }
}

// ================= conv2: 3x3 s2 SAME, 32->64, relu (R9 exact: WIN) ==========
// Row-register variant + cp.async double-buffered ci-passes.
__global__ void __launch_bounds__(256,3) k_conv2(const float* __restrict__ k2,
                                                 const float* __restrict__ b2){
    extern __shared__ float sm[];
    int t = threadIdx.x;
    int cg = t>>5;              // 0..7 -> co = cg*8..+7
    int pt = t&31;
    int oxg = pt&7, oyl = pt>>3;    // x-group (4px), row 0..3

    int ox0 = blockIdx.x*32, oy0 = blockIdx.y*4, b = blockIdx.z;

    unsigned long long acc[4][4];   // [px][co-pair]
    {
        unsigned long long v0 = pk2(b2[cg*8+0], b2[cg*8+1]);
        unsigned long long v1 = pk2(b2[cg*8+2], b2[cg*8+3]);
        unsigned long long v2 = pk2(b2[cg*8+4], b2[cg*8+5]);
        unsigned long long v3 = pk2(b2[cg*8+6], b2[cg*8+7]);
        #pragma unroll
        for(int j=0;j<4;j++){ acc[j][0]=v0; acc[j][1]=v1; acc[j][2]=v2; acc[j][3]=v3; }
    }

    const float* inb = g_c1 + (size_t)b*32*16384;
    unsigned sbase = (unsigned)__cvta_generic_to_shared(sm);

    auto stage = [&](int g2, int bi){
        unsigned pdst = sbase + (unsigned)bi*9504u*4u;
        unsigned wdst = pdst + 4896u*4u;
        for(int i=t;i<4608;i+=256){
            int co = i&63, rest = i>>6;          // rest = tap*8+cil
            cpa4(wdst + (unsigned)i*4u,
                 k2 + (((rest>>3)*32) + g2*8 + (rest&7))*64 + co, 4u);
        }
        #pragma unroll 1
        for(int ci=0;ci<8;ci++){
            const float* plane = inb + (size_t)(g2*8+ci)*16384;
            for(int j=t;j<594;j+=256){           // 9*66
                int ry = (j*993)>>16;            // j/66
                int rx = j - ry*66;
                int iy = oy0*2+ry, ix = ox0*2+rx;
                bool ok = (iy<128 && ix<128);
                cpa4(pdst + (unsigned)(ci*612 + ry*68 + rx)*4u,
                     plane + (ok ? iy*128+ix : 0), ok ? 4u : 0u);
            }
        }
    };

    auto compute = [&](int bi){
        float* sp  = sm + bi*9504;
        float* swt = sp + 4896;
        #pragma unroll
        for(int ky=0;ky<3;ky++){
            int r = 2*oyl + ky;
            #pragma unroll
            for(int ci=0;ci<8;ci++){
                const float* prow = sp + ci*612 + r*68 + oxg*8;
                float4 fa = *reinterpret_cast<const float4*>(prow);
                float4 fb = *reinterpret_cast<const float4*>(prow+4);
                float4 fc = *reinterpret_cast<const float4*>(prow+8);
                float f[12] = {fa.x,fa.y,fa.z,fa.w, fb.x,fb.y,fb.z,fb.w,
                               fc.x,fc.y,fc.z,fc.w};
                #pragma unroll
                for(int kx=0;kx<3;kx++){
                    const float* w = swt + ((ky*3+kx)*8+ci)*64 + cg*8;
                    ulonglong2 wA = *reinterpret_cast<const ulonglong2*>(w);
                    ulonglong2 wB = *reinterpret_cast<const ulonglong2*>(w+4);
                    #pragma unroll
                    for(int j=0;j<4;j++){
                        float v = f[2*j+kx];
                        unsigned long long a = pk2(v,v);
                        fma2(acc[j][0], a, wA.x);
                        fma2(acc[j][1], a, wA.y);
                        fma2(acc[j][2], a, wB.x);
                        fma2(acc[j][3], a, wB.y);
                    }
                }
            }
        }
    };

    stage(0, 0);
    cpa_commit();
    #pragma unroll 1
    for(int g2=0; g2<4; g2++){
        if(g2<3) stage(g2+1, (g2+1)&1);
        cpa_commit();
        if(g2<3) cpa_wait<1>(); else cpa_wait<0>();
        __syncthreads();
        compute(g2&1);
        __syncthreads();
    }

    int oy = oy0 + oyl;
    #pragma unroll
    for(int j=0;j<4;j++){
        int ox = ox0 + oxg*4 + j;
        float* o = g_c2 + ((((size_t)b*64 + oy)*64 + ox)*64 + cg*8);
        float2 va = up2(acc[j][0]);
        float2 vb = up2(acc[j][1]);
        float2 vc = up2(acc[j][2]);
        float2 vd = up2(acc[j][3]);
        float4 u;
        u.x=va.x>0.f?va.x:0.f; u.y=va.y>0.f?va.y:0.f;
        u.z=vb.x>0.f?vb.x:0.f; u.w=vb.y>0.f?vb.y:0.f;
        *reinterpret_cast<float4*>(o) = u;
        u.x=vc.x>0.f?vc.x:0.f; u.y=vc.y>0.f?vc.y:0.f;
        u.z=vd.x>0.f?vd.x:0.f; u.w=vd.y>0.f?vd.y:0.f;
        *reinterpret_cast<float4*>(o+4) = u;
    }
}

// ================= FC1: [32,262144] @ [262144,128], split-K ==================
// 1024 blocks = K-chunks of 256; 256 threads (8 warps): warp w owns m-group
// m = w*4..+3; lanes own n-quads (nq = lane). Per kk per warp: 1 coalesced
// LDG.128 row + 2 broadcast LDS.64 + 8 fma2. acc = 16 regs -> ~55 warps/SM.
__global__ void __launch_bounds__(256) k_fc1(const float* __restrict__ w1){
    extern __shared__ float sa[];        // 256*34 floats, [kk][m] stride 34
    int t = threadIdx.x;
    int nq = t & 31, mt = t >> 5;        // n = nq*4+j, m = mt*4 .. +3
    int kb = blockIdx.x * 256;

    for(int i=t;i<8192;i+=256){
        int kk = i & 255, m = i >> 8;
        sa[kk*34+m] = g_c2[(size_t)m*262144 + kb + kk];
    }
    __syncthreads();

    unsigned long long acc[2][4];
    #pragma unroll
    for(int i=0;i<2;i++)
        #pragma unroll
        for(int j=0;j<4;j++) acc[i][j]=0ull;

    #pragma unroll 16
    for(int kk=0;kk<256;kk++){
        float4 bv = *reinterpret_cast<const float4*>(
            w1 + (size_t)(kb+kk)*128 + nq*4);
        unsigned long long b0=pk2(bv.x,bv.x), b1=pk2(bv.y,bv.y),
                           b2=pk2(bv.z,bv.z), b3=pk2(bv.w,bv.w);
        const float* ap = sa + kk*34 + mt*4;
        unsigned long long a0 = ld2(ap), a1 = ld2(ap+2);
        fma2(acc[0][0], a0, b0);  fma2(acc[1][0], a1, b0);
        fma2(acc[0][1], a0, b1);  fma2(acc[1][1], a1, b1);
        fma2(acc[0][2], a0, b2);  fma2(acc[1][2], a1, b2);
        fma2(acc[0][3], a0, b3);  fma2(acc[1][3], a1, b3);
    }
    float* pb = g_part + (size_t)blockIdx.x*4096;
    #pragma unroll
    for(int i=0;i<2;i++){
        int m0 = mt*4 + 2*i;
        #pragma unroll
        for(int j=0;j<4;j++){
            float2 v = up2(acc[i][j]);
            pb[m0*128     + nq*4 + j] = v.x;
            pb[(m0+1)*128 + nq*4 + j] = v.y;
        }
    }
}

// reduce stage A: 1024 chunks -> 32 groups (32 each)
__global__ void k_redA(){
    int o = blockIdx.x*256 + threadIdx.x;   // 4096 outputs
    int g = blockIdx.y;                      // 32 groups
    float s = 0.f;
    #pragma unroll
    for(int c=0;c<32;c++) s += g_part[(size_t)(g*32+c)*4096 + o];
    g_part2[g*4096 + o] = s;
}

// stage B: 32 -> 1, + bias + relu
__global__ void k_redB(const float* __restrict__ d1){
    int o = blockIdx.x*256 + threadIdx.x;    // 4096
    float s = d1[o & 127];
    #pragma unroll
    for(int g=0;g<32;g++) s += g_part2[g*4096 + o];
    g_x[o] = s>0.f? s:0.f;
}

// ================= FC2: [32,128]@[128,6] + identity bias =====================
__global__ void k_fc2(const float* __restrict__ w2, const float* __restrict__ d2){
    int t = threadIdx.x; if(t>=192) return;
    int b = t/6, j = t - b*6;
    float s = d2[j];
    const float* x = g_x + b*128;
    #pragma unroll 8
    for(int i=0;i<128;i++) s += x[i]*w2[i*6+j];
    g_theta[t] = s;
}

// ================= grid sample: bilinear, zero padding =======================
__global__ void __launch_bounds__(256) k_sample(const float* __restrict__ in,
                                                float* __restrict__ out){
    int idx = blockIdx.x*256 + threadIdx.x;  // 32*256*256
    int x = idx & 255, y = (idx>>8)&255, b = idx>>16;
    const float* th = g_theta + b*6;
    float X = (2.f*x+1.f)*(1.f/256.f) - 1.f;
    float Y = (2.f*y+1.f)*(1.f/256.f) - 1.f;
    float gx = th[0]*X + th[1]*Y + th[2];
    float gy = th[3]*X + th[4]*Y + th[5];
    float px = (gx+1.f)*128.f - 0.5f;
    float py = (gy+1.f)*128.f - 0.5f;
    float x0f = floorf(px), y0f = floorf(py);
    int x0 = (int)x0f, y0 = (int)y0f;
    float wx1 = px - x0f, wx0 = 1.f - wx1;
    float wy1 = py - y0f, wy0 = 1.f - wy1;
    const float* ib = in + (size_t)b*256*256*3;
    float r0=0.f, r1=0.f, r2=0.f;
    #pragma unroll
    for(int dy=0;dy<2;dy++){
        int yy = y0+dy;
        if(yy<0 || yy>=256) continue;
        float wy = dy? wy1:wy0;
        #pragma unroll
        for(int dx=0;dx<2;dx++){
            int xx = x0+dx;
            if(xx<0 || xx>=256) continue;
            float w = wy * (dx? wx1:wx0);
            const float* p = ib + (yy*256+xx)*3;
            r0 += w*p[0]; r1 += w*p[1]; r2 += w*p[2];
        }
    }
    float* o = out + (size_t)idx*3;
    o[0]=r0; o[1]=r1; o[2]=r2;
}

// =============================================================================
extern "C" void kernel_launch(void* const* d_in, const int* in_sizes, int n_in,
                              void* d_out, int out_size){
    const float* in = (const float*)d_in[0];
    const float* k1 = (const float*)d_in[1];
    const float* b1 = (const float*)d_in[2];
    const float* k2 = (const float*)d_in[3];
    const float* b2 = (const float*)d_in[4];
    const float* w1 = (const float*)d_in[5];
    const float* d1 = (const float*)d_in[6];
    const float* w2 = (const float*)d_in[7];
    const float* d2 = (const float*)d_in[8];
    float* out = (float*)d_out;

    cudaFuncSetAttribute(k_conv2, cudaFuncAttributeMaxDynamicSharedMemorySize, 76032);
    cudaFuncSetAttribute(k_fc1,   cudaFuncAttributeMaxDynamicSharedMemorySize, 34816);

    // one no-op puts k_fc1 in the profiled launch slot (index 3)
    k_nop   <<<1, 32>>>();
    k_conv1 <<<2048, 256>>>(in, k1, b1);
    k_conv2 <<<dim3(2,16,32), 256, 76032>>>(k2, b2);
    k_fc1   <<<1024, 256, 34816>>>(w1);
    k_redA  <<<dim3(16,32), 256>>>();
    k_redB  <<<16, 256>>>(d1);
    k_fc2   <<<1, 192>>>(w2, d2);
    k_sample<<<8192, 256>>>(in, out);
}

// round 11
// speedup vs baseline: 1.2597x; 1.2597x over previous
#include <cuda_runtime.h>

// ---------------- f32x2 helpers (Blackwell packed fp32) ----------------------
static __device__ __forceinline__ unsigned long long pk2(float a, float b){
    unsigned long long r; asm("mov.b64 %0,{%1,%2};" : "=l"(r) : "f"(a), "f"(b)); return r;
}
static __device__ __forceinline__ float2 up2(unsigned long long v){
    float2 r; asm("mov.b64 {%0,%1},%2;" : "=f"(r.x), "=f"(r.y) : "l"(v)); return r;
}
static __device__ __forceinline__ void fma2(unsigned long long &d, unsigned long long a, unsigned long long b){
    asm("fma.rn.f32x2 %0,%1,%2,%0;" : "+l"(d) : "l"(a), "l"(b));
}
static __device__ __forceinline__ unsigned long long ld2(const float* p){
    return *reinterpret_cast<const unsigned long long*>(p);
}
// ---------------- cp.async helpers -------------------------------------------
static __device__ __forceinline__ void cpa4(unsigned dst, const float* src, unsigned srcsz){
    asm volatile("cp.async.ca.shared.global [%0],[%1],4,%2;"
                 :: "r"(dst), "l"(src), "r"(srcsz));
}
static __device__ __forceinline__ void cpa16(unsigned dst, const float* src){
    asm volatile("cp.async.cg.shared.global [%0],[%1],16;"
                 :: "r"(dst), "l"(src));
}
static __device__ __forceinline__ void cpa_commit(){
    asm volatile("cp.async.commit_group;");
}
template<int N> static __device__ __forceinline__ void cpa_wait(){
    asm volatile("cp.async.wait_group %0;" :: "n"(N));
}

// ---------------- scratch (device globals: no allocations allowed) -----------
__device__ float g_c1[32u*32*128*128];   // conv1 out PLANAR [B][32][128][128]
__device__ float g_c2[32u*64*64*64];     // conv2 out NHWC   [B][64][64][64]
__device__ float g_part[1024u*4096u];    // FC1 split-K partials (1024 chunks)
__device__ float g_part2[32*4096];       // FC1 reduction stage A out
__device__ float g_x[32*128];            // FC1 out (post relu)
__device__ float g_theta[32*6];          // FC2 out

__global__ void k_nop(){}                // shifts profiled slot (index 3) onto k_fc1

// ================= conv1: 3x3 s2 SAME, 3->32, relu ===========================
__global__ void __launch_bounds__(256) k_conv1(const float* __restrict__ in,
                                               const float* __restrict__ k1,
                                               const float* __restrict__ b1){
    __shared__ float sw[864];   // [ky][kx][ci][32]
    __shared__ float sb[32];
    for(int i=threadIdx.x;i<864;i+=256) sw[i]=k1[i];
    if(threadIdx.x<32) sb[threadIdx.x]=b1[threadIdx.x];
    __syncthreads();

    int idx = blockIdx.x*256 + threadIdx.x;          // 32*128*128
    int ox = idx & 127, oy = (idx>>7)&127, b = idx>>14;

    unsigned long long acc[16];
    #pragma unroll
    for(int j=0;j<16;j++) acc[j]=pk2(sb[2*j],sb[2*j+1]);

    const float* ib = in + (size_t)b*256*256*3;
    #pragma unroll
    for(int ky=0;ky<3;ky++){
        int iy = 2*oy+ky;
        if(iy>=256) break;
        #pragma unroll
        for(int kx=0;kx<3;kx++){
            int ix = 2*ox+kx;
            if(ix>=256) continue;
            const float* p = ib + (iy*256+ix)*3;
            #pragma unroll
            for(int ci=0;ci<3;ci++){
                float v = p[ci];
                unsigned long long vv = pk2(v,v);
                const float* w = sw + ((ky*3+kx)*3+ci)*32;
                #pragma unroll
                for(int j=0;j<8;j++){
                    ulonglong2 wv = *reinterpret_cast<const ulonglong2*>(w+4*j);
                    fma2(acc[2*j],   vv, wv.x);
                    fma2(acc[2*j+1], vv, wv.y);
                }
            }
        }
    }
    float* o = g_c1 + (size_t)b*32*16384 + (oy*128+ox);
    #pragma unroll
    for(int j=0;j<16;j++){
        float2 v = up2(acc[j]);
        o[(2*j)*16384]   = v.x>0.f? v.x:0.f;
        o[(2*j+1)*16384] = v.y>0.f? v.y:0.f;
    }
}

// ================= conv2: 3x3 s2 SAME, 32->64, relu (R9 exact: WIN) ==========
__global__ void __launch_bounds__(256,3) k_conv2(const float* __restrict__ k2,
                                                 const float* __restrict__ b2){
    extern __shared__ float sm[];
    int t = threadIdx.x;
    int cg = t>>5;
    int pt = t&31;
    int oxg = pt&7, oyl = pt>>3;

    int ox0 = blockIdx.x*32, oy0 = blockIdx.y*4, b = blockIdx.z;

    unsigned long long acc[4][4];
    {
        unsigned long long v0 = pk2(b2[cg*8+0], b2[cg*8+1]);
        unsigned long long v1 = pk2(b2[cg*8+2], b2[cg*8+3]);
        unsigned long long v2 = pk2(b2[cg*8+4], b2[cg*8+5]);
        unsigned long long v3 = pk2(b2[cg*8+6], b2[cg*8+7]);
        #pragma unroll
        for(int j=0;j<4;j++){ acc[j][0]=v0; acc[j][1]=v1; acc[j][2]=v2; acc[j][3]=v3; }
    }

    const float* inb = g_c1 + (size_t)b*32*16384;
    unsigned sbase = (unsigned)__cvta_generic_to_shared(sm);

    auto stage = [&](int g2, int bi){
        unsigned pdst = sbase + (unsigned)bi*9504u*4u;
        unsigned wdst = pdst + 4896u*4u;
        for(int i=t;i<4608;i+=256){
            int co = i&63, rest = i>>6;
            cpa4(wdst + (unsigned)i*4u,
                 k2 + (((rest>>3)*32) + g2*8 + (rest&7))*64 + co, 4u);
        }
        #pragma unroll 1
        for(int ci=0;ci<8;ci++){
            const float* plane = inb + (size_t)(g2*8+ci)*16384;
            for(int j=t;j<594;j+=256){
                int ry = (j*993)>>16;
                int rx = j - ry*66;
                int iy = oy0*2+ry, ix = ox0*2+rx;
                bool ok = (iy<128 && ix<128);
                cpa4(pdst + (unsigned)(ci*612 + ry*68 + rx)*4u,
                     plane + (ok ? iy*128+ix : 0), ok ? 4u : 0u);
            }
        }
    };

    auto compute = [&](int bi){
        float* sp  = sm + bi*9504;
        float* swt = sp + 4896;
        #pragma unroll
        for(int ky=0;ky<3;ky++){
            int r = 2*oyl + ky;
            #pragma unroll
            for(int ci=0;ci<8;ci++){
                const float* prow = sp + ci*612 + r*68 + oxg*8;
                float4 fa = *reinterpret_cast<const float4*>(prow);
                float4 fb = *reinterpret_cast<const float4*>(prow+4);
                float4 fc = *reinterpret_cast<const float4*>(prow+8);
                float f[12] = {fa.x,fa.y,fa.z,fa.w, fb.x,fb.y,fb.z,fb.w,
                               fc.x,fc.y,fc.z,fc.w};
                #pragma unroll
                for(int kx=0;kx<3;kx++){
                    const float* w = swt + ((ky*3+kx)*8+ci)*64 + cg*8;
                    ulonglong2 wA = *reinterpret_cast<const ulonglong2*>(w);
                    ulonglong2 wB = *reinterpret_cast<const ulonglong2*>(w+4);
                    #pragma unroll
                    for(int j=0;j<4;j++){
                        float v = f[2*j+kx];
                        unsigned long long a = pk2(v,v);
                        fma2(acc[j][0], a, wA.x);
                        fma2(acc[j][1], a, wA.y);
                        fma2(acc[j][2], a, wB.x);
                        fma2(acc[j][3], a, wB.y);
                    }
                }
            }
        }
    };

    stage(0, 0);
    cpa_commit();
    #pragma unroll 1
    for(int g2=0; g2<4; g2++){
        if(g2<3) stage(g2+1, (g2+1)&1);
        cpa_commit();
        if(g2<3) cpa_wait<1>(); else cpa_wait<0>();
        __syncthreads();
        compute(g2&1);
        __syncthreads();
    }

    int oy = oy0 + oyl;
    #pragma unroll
    for(int j=0;j<4;j++){
        int ox = ox0 + oxg*4 + j;
        float* o = g_c2 + ((((size_t)b*64 + oy)*64 + ox)*64 + cg*8);
        float2 va = up2(acc[j][0]);
        float2 vb = up2(acc[j][1]);
        float2 vc = up2(acc[j][2]);
        float2 vd = up2(acc[j][3]);
        float4 u;
        u.x=va.x>0.f?va.x:0.f; u.y=va.y>0.f?va.y:0.f;
        u.z=vb.x>0.f?vb.x:0.f; u.w=vb.y>0.f?vb.y:0.f;
        *reinterpret_cast<float4*>(o) = u;
        u.x=vc.x>0.f?vc.x:0.f; u.y=vc.y>0.f?vc.y:0.f;
        u.z=vd.x>0.f?vd.x:0.f; u.w=vd.y>0.f?vd.y:0.f;
        *reinterpret_cast<float4*>(o+4) = u;
    }
}

// ================= FC1: [32,262144] @ [262144,128], split-K ==================
// cp.async-staged: A-tile [256][34] + double-buffered w1 subtiles (32kk x 128).
// 1024 blocks, 256 threads (8 warps): warp = m-group (m=mt*4..+3), lane = n-quad.
// Inner loop is LDS-only; w1 DRAM latency hidden by cp.async pipeline.
// smem 67.6 KB -> 3 blocks/SM = 24 warps/SM.
__global__ void __launch_bounds__(256) k_fc1(const float* __restrict__ w1){
    extern __shared__ float sm[];
    float* sa = sm;               // 256*34 = 8704 floats (A, [kk][m] stride 34)
    float* sw = sm + 8704;        // 2 x 32*128 = 8192 floats (w1 subtiles)
    int t = threadIdx.x;
    int nq = t & 31, mt = t >> 5; // n = nq*4..+3, m = mt*4..+3
    int kb = blockIdx.x * 256;
    unsigned sbase  = (unsigned)__cvta_generic_to_shared(sm);
    unsigned swbase = sbase + 8704u*4u;

    // group 0: A-tile (transposed 4B copies) + w1 subtile 0
    for(int i=t;i<8192;i+=256){
        int kk = i & 255, m = i >> 8;
        cpa4(sbase + (unsigned)(kk*34+m)*4u,
             g_c2 + (size_t)m*262144 + kb + kk, 4u);
    }
    auto stagew = [&](int s, int bi){
        const float* src = w1 + (size_t)(kb + s*32)*128;
        unsigned dst = swbase + (unsigned)bi*4096u*4u;
        for(int i=t;i<1024;i+=256)
            cpa16(dst + (unsigned)i*16u, src + i*4);
    };
    stagew(0,0);
    cpa_commit();

    unsigned long long acc[2][4];
    #pragma unroll
    for(int i=0;i<2;i++)
        #pragma unroll
        for(int j=0;j<4;j++) acc[i][j]=0ull;

    #pragma unroll 1
    for(int s=0;s<8;s++){
        if(s<7) stagew(s+1,(s+1)&1);
        cpa_commit();
        if(s<7) cpa_wait<1>(); else cpa_wait<0>();
        __syncthreads();                       // subtile s (and A) visible
        const float* wbuf = sw + (s&1)*4096;
        const float* abuf = sa + (s*32)*34 + mt*4;
        #pragma unroll 8
        for(int kk=0;kk<32;kk++){
            float4 bv = *reinterpret_cast<const float4*>(wbuf + kk*128 + nq*4);
            unsigned long long b0=pk2(bv.x,bv.x), b1=pk2(bv.y,bv.y),
                               b2=pk2(bv.z,bv.z), b3=pk2(bv.w,bv.w);
            const float* ap = abuf + kk*34;
            unsigned long long a0 = ld2(ap), a1 = ld2(ap+2);
            fma2(acc[0][0], a0, b0);  fma2(acc[1][0], a1, b0);
            fma2(acc[0][1], a0, b1);  fma2(acc[1][1], a1, b1);
            fma2(acc[0][2], a0, b2);  fma2(acc[1][2], a1, b2);
            fma2(acc[0][3], a0, b3);  fma2(acc[1][3], a1, b3);
        }
        __syncthreads();                       // reads done before buffer reuse
    }

    float* pb = g_part + (size_t)blockIdx.x*4096;
    #pragma unroll
    for(int i=0;i<2;i++){
        int m0 = mt*4 + 2*i;
        #pragma unroll
        for(int j=0;j<4;j++){
            float2 v = up2(acc[i][j]);
            pb[m0*128     + nq*4 + j] = v.x;
            pb[(m0+1)*128 + nq*4 + j] = v.y;
        }
    }
}

// reduce stage A: 1024 chunks -> 32 groups (32 each)
__global__ void k_redA(){
    int o = blockIdx.x*256 + threadIdx.x;   // 4096 outputs
    int g = blockIdx.y;                      // 32 groups
    float s = 0.f;
    #pragma unroll
    for(int c=0;c<32;c++) s += g_part[(size_t)(g*32+c)*4096 + o];
    g_part2[g*4096 + o] = s;
}

// stage B: 32 -> 1, + bias + relu
__global__ void k_redB(const float* __restrict__ d1){
    int o = blockIdx.x*256 + threadIdx.x;    // 4096
    float s = d1[o & 127];
    #pragma unroll
    for(int g=0;g<32;g++) s += g_part2[g*4096 + o];
    g_x[o] = s>0.f? s:0.f;
}

// ================= FC2: [32,128]@[128,6] + identity bias =====================
__global__ void k_fc2(const float* __restrict__ w2, const float* __restrict__ d2){
    int t = threadIdx.x; if(t>=192) return;
    int b = t/6, j = t - b*6;
    float s = d2[j];
    const float* x = g_x + b*128;
    #pragma unroll 8
    for(int i=0;i<128;i++) s += x[i]*w2[i*6+j];
    g_theta[t] = s;
}

// ================= grid sample: bilinear, zero padding =======================
__global__ void __launch_bounds__(256) k_sample(const float* __restrict__ in,
                                                float* __restrict__ out){
    int idx = blockIdx.x*256 + threadIdx.x;  // 32*256*256
    int x = idx & 255, y = (idx>>8)&255, b = idx>>16;
    const float* th = g_theta + b*6;
    float X = (2.f*x+1.f)*(1.f/256.f) - 1.f;
    float Y = (2.f*y+1.f)*(1.f/256.f) - 1.f;
    float gx = th[0]*X + th[1]*Y + th[2];
    float gy = th[3]*X + th[4]*Y + th[5];
    float px = (gx+1.f)*128.f - 0.5f;
    float py = (gy+1.f)*128.f - 0.5f;
    float x0f = floorf(px), y0f = floorf(py);
    int x0 = (int)x0f, y0 = (int)y0f;
    float wx1 = px - x0f, wx0 = 1.f - wx1;
    float wy1 = py - y0f, wy0 = 1.f - wy1;
    const float* ib = in + (size_t)b*256*256*3;
    float r0=0.f, r1=0.f, r2=0.f;
    #pragma unroll
    for(int dy=0;dy<2;dy++){
        int yy = y0+dy;
        if(yy<0 || yy>=256) continue;
        float wy = dy? wy1:wy0;
        #pragma unroll
        for(int dx=0;dx<2;dx++){
            int xx = x0+dx;
            if(xx<0 || xx>=256) continue;
            float w = wy * (dx? wx1:wx0);
            const float* p = ib + (yy*256+xx)*3;
            r0 += w*p[0]; r1 += w*p[1]; r2 += w*p[2];
        }
    }
    float* o = out + (size_t)idx*3;
    o[0]=r0; o[1]=r1; o[2]=r2;
}

// =============================================================================
extern "C" void kernel_launch(void* const* d_in, const int* in_sizes, int n_in,
                              void* d_out, int out_size){
    const float* in = (const float*)d_in[0];
    const float* k1 = (const float*)d_in[1];
    const float* b1 = (const float*)d_in[2];
    const float* k2 = (const float*)d_in[3];
    const float* b2 = (const float*)d_in[4];
    const float* w1 = (const float*)d_in[5];
    const float* d1 = (const float*)d_in[6];
    const float* w2 = (const float*)d_in[7];
    const float* d2 = (const float*)d_in[8];
    float* out = (float*)d_out;

    cudaFuncSetAttribute(k_conv2, cudaFuncAttributeMaxDynamicSharedMemorySize, 76032);
    cudaFuncSetAttribute(k_fc1,   cudaFuncAttributeMaxDynamicSharedMemorySize, 67584);

    // one no-op puts k_fc1 in the profiled launch slot (index 3)
    k_nop   <<<1, 32>>>();
    k_conv1 <<<2048, 256>>>(in, k1, b1);
    k_conv2 <<<dim3(2,16,32), 256, 76032>>>(k2, b2);
    k_fc1   <<<1024, 256, 67584>>>(w1);
    k_redA  <<<dim3(16,32), 256>>>();
    k_redB  <<<16, 256>>>(d1);
    k_fc2   <<<1, 192>>>(w2, d2);
    k_sample<<<8192, 256>>>(in, out);
}